// round 5
// baseline (speedup 1.0000x reference)
#include <cuda_runtime.h>
#include <cuda_fp16.h>

// OLCNN fused grouped-MLP, round 4.
// R3 post-mortem: LDC.64 constant-port (rt 8/SMSP) was the kernel-time-exact
// bottleneck. Fixes:
//   - weights moved to smem (broadcast LDS.64, rt 2/SMSP)
//   - 4 elems/thread (2 f32x2 pairs) -> each weight load feeds 2 FFMA2
//   - fp16 input staging (stride 82 halfs: 4B-aligned, conflict-free)
//   - folded tanh network (validated R2/R3), gPrep read directly (no const copy)

typedef unsigned long long ull;

#define NT    64      // threads per block
#define EPB   256     // elements per block (4 per thread)
#define KDIM  81
#define KPAD  82      // padded element stride in halfs (164 B, 4B-aligned)

// packed-weight blob offsets (ull units)
#define OFF_WC 0
#define OFF_BC 729
#define OFF_WH 810
#define OFF_BH 1053
#define OFF_WM 1080
#define OFF_BM 1188
#define OFF_WO 1200
#define OFF_BO 1216
#define NPREP  1220

__device__ ull gPrep[NPREP];

__device__ __forceinline__ ull dupf(float v) {
    unsigned int b = __float_as_uint(v);
    return ((ull)b << 32) | (ull)b;
}

// Fold sigmoid(a)=0.5*tanh(a/2)+0.5 through the network (validated R2/R3).
__global__ void prep_kernel(const float* __restrict__ Wc, const float* __restrict__ bc,
                            const float* __restrict__ Wh, const float* __restrict__ bh,
                            const float* __restrict__ Wm, const float* __restrict__ bm,
                            const float* __restrict__ Wo, const float* __restrict__ bo) {
    int t = threadIdx.x;
    for (int i = t; i < 729; i += blockDim.x) gPrep[OFF_WC + i] = dupf(0.5f  * Wc[i]);
    for (int i = t; i < 81;  i += blockDim.x) gPrep[OFF_BC + i] = dupf(0.5f  * bc[i]);
    for (int i = t; i < 243; i += blockDim.x) gPrep[OFF_WH + i] = dupf(0.25f * Wh[i]);
    for (int i = t; i < 27;  i += blockDim.x) {
        float s = 0.f;
        #pragma unroll
        for (int p = 0; p < 9; p++) s += Wh[i * 9 + p];
        gPrep[OFF_BH + i] = dupf(0.5f * bh[i] + 0.25f * s);
    }
    for (int i = t; i < 108; i += blockDim.x) gPrep[OFF_WM + i] = dupf(0.25f * Wm[i]);
    for (int i = t; i < 12;  i += blockDim.x) {
        float s = 0.f;
        #pragma unroll
        for (int p = 0; p < 9; p++) s += Wm[i * 9 + p];
        gPrep[OFF_BM + i] = dupf(0.5f * bm[i] + 0.25f * s);
    }
    for (int i = t; i < 16;  i += blockDim.x) gPrep[OFF_WO + i] = dupf(0.5f * Wo[i]);
    for (int i = t; i < 4;   i += blockDim.x) {
        float s = 0.f;
        #pragma unroll
        for (int p = 0; p < 4; p++) s += Wo[i * 4 + p];
        gPrep[OFF_BO + i] = dupf(bo[i] + 0.5f * s);
    }
}

__device__ __forceinline__ ull ffma2(ull a, ull b, ull c) {
    ull d;
    asm("fma.rn.f32x2 %0, %1, %2, %3;" : "=l"(d) : "l"(a), "l"(b), "l"(c));
    return d;
}
__device__ __forceinline__ ull pack2(float lo, float hi) {
    ull r;
    asm("mov.b64 %0, {%1, %2};" : "=l"(r) : "f"(lo), "f"(hi));
    return r;
}
__device__ __forceinline__ void unpack2(ull v, float& lo, float& hi) {
    asm("mov.b64 {%0, %1}, %2;" : "=f"(lo), "=f"(hi) : "l"(v));
}
__device__ __forceinline__ ull tanh2(ull v) {
    float lo, hi;
    unpack2(v, lo, hi);
    asm("tanh.approx.f32 %0, %0;" : "+f"(lo));
    asm("tanh.approx.f32 %0, %0;" : "+f"(hi));
    return pack2(lo, hi);
}

// dynamic smem: [ ws: NPREP ull ][ xs: EPB*KPAD half ]
#define SMEM_BYTES (NPREP * 8 + EPB * KPAD * 2)

__global__ __launch_bounds__(NT, 4)
void olcnn_kernel(const float* __restrict__ x, float* __restrict__ out) {
    extern __shared__ ull smem_raw[];
    ull*    ws = smem_raw;
    __half* xs = reinterpret_cast<__half*>(smem_raw + NPREP);

    const int tid = threadIdx.x;
    const long long blk = blockIdx.x;

    // ---- stage weights (L2-hot, 9.76 KB) ----
    #pragma unroll
    for (int i = 0; i < NPREP / NT + 1; i++) {
        int idx = i * NT + tid;
        if (idx < NPREP) ws[idx] = gPrep[idx];
    }

    // ---- stage inputs: coalesced float4 -> fp16, element stride KPAD ----
    {
        const float4* __restrict__ src =
            reinterpret_cast<const float4*>(x + blk * (long long)(EPB * KDIM));
        for (int i = tid; i < (EPB * KDIM) / 4; i += NT) {
            float4 v = src[i];
            int f = i * 4;
            int e = f / KDIM;           // const-div
            int k = f - e * KDIM;
            __half* d = xs + e * KPAD + k;
            // k may cross the 81-boundary within this float4
            if (k <= KDIM - 4) {
                d[0] = __float2half_rn(v.x);
                d[1] = __float2half_rn(v.y);
                d[2] = __float2half_rn(v.z);
                d[3] = __float2half_rn(v.w);
            } else {
                float vv[4] = {v.x, v.y, v.z, v.w};
                #pragma unroll
                for (int j = 0; j < 4; j++) {
                    int kk = k + j, ee = e;
                    if (kk >= KDIM) { kk -= KDIM; ee++; }
                    xs[ee * KPAD + kk] = __float2half_rn(vv[j]);
                }
            }
        }
    }
    __syncthreads();

    // thread handles 2 packed pairs: A={tid, tid+64}, B={tid+128, tid+192}
    const __half* __restrict__ xa0 = xs + (tid          ) * KPAD;
    const __half* __restrict__ xa1 = xs + (tid + NT     ) * KPAD;
    const __half* __restrict__ xb0 = xs + (tid + 2 * NT ) * KPAD;
    const __half* __restrict__ xb1 = xs + (tid + 3 * NT ) * KPAD;

    ull lgA[4], lgB[4];
    #pragma unroll
    for (int c = 0; c < 4; c++) { lgA[c] = ws[OFF_BO + c]; lgB[c] = lgA[c]; }

    #pragma unroll
    for (int G = 0; G < 3; G++) {
        ull hA[9], hB[9];

        #pragma unroll
        for (int s = 0; s < 3; s++) {
            const int g  = 3 * G + s;
            const int gr = g / 3, gc = g % 3;

            ull pxA[9], pxB[9];
            #pragma unroll
            for (int p = 0; p < 9; p++) {
                const int k = (3 * gr + p / 3) * 9 + (3 * gc + p % 3);
                pxA[p] = pack2(__half2float(xa0[k]), __half2float(xa1[k]));
                pxB[p] = pack2(__half2float(xb0[k]), __half2float(xb1[k]));
            }

            // conv: 9 kernels -> tanh
            ull fA[9], fB[9];
            #pragma unroll
            for (int k = 0; k < 9; k++) {
                ull accA = ws[OFF_BC + g * 9 + k];
                ull accB = accA;
                #pragma unroll
                for (int p = 0; p < 9; p++) {
                    ull w = ws[OFF_WC + (g * 9 + k) * 9 + p];
                    accA = ffma2(pxA[p], w, accA);
                    accB = ffma2(pxB[p], w, accB);
                }
                fA[k] = tanh2(accA);
                fB[k] = tanh2(accB);
            }

            // hidden: 3 neurons -> tanh
            #pragma unroll
            for (int n = 0; n < 3; n++) {
                ull accA = ws[OFF_BH + g * 3 + n];
                ull accB = accA;
                #pragma unroll
                for (int k = 0; k < 9; k++) {
                    ull w = ws[OFF_WH + (g * 3 + n) * 9 + k];
                    accA = ffma2(fA[k], w, accA);
                    accB = ffma2(fB[k], w, accB);
                }
                hA[s * 3 + n] = tanh2(accA);
                hB[s * 3 + n] = tanh2(accB);
            }
        }

        // middle group G: 4 neurons -> tanh -> fold into logits
        #pragma unroll
        for (int n = 0; n < 4; n++) {
            ull accA = ws[OFF_BM + G * 4 + n];
            ull accB = accA;
            #pragma unroll
            for (int p = 0; p < 9; p++) {
                ull w = ws[OFF_WM + (G * 4 + n) * 9 + p];
                accA = ffma2(hA[p], w, accA);
                accB = ffma2(hB[p], w, accB);
            }
            ull mA = tanh2(accA), mB = tanh2(accB);

            ull wo = ws[OFF_WO + G * 4 + n];
            lgA[G] = ffma2(mA, wo, lgA[G]);
            lgB[G] = ffma2(mB, wo, lgB[G]);
            if (G == 0) {
                ull wo3 = ws[OFF_WO + 3 * 4 + n];
                lgA[3] = ffma2(mA, wo3, lgA[3]);
                lgB[3] = ffma2(mB, wo3, lgB[3]);
            }
        }
    }

    float a0[4], a1[4], b0[4], b1[4];
    #pragma unroll
    for (int c = 0; c < 4; c++) {
        unpack2(lgA[c], a0[c], a1[c]);
        unpack2(lgB[c], b0[c], b1[c]);
    }

    float4* __restrict__ o4 = reinterpret_cast<float4*>(out) + blk * EPB;
    o4[tid         ] = make_float4(a0[0], a0[1], a0[2], a0[3]);
    o4[tid +     NT] = make_float4(a1[0], a1[1], a1[2], a1[3]);
    o4[tid + 2 * NT] = make_float4(b0[0], b0[1], b0[2], b0[3]);
    o4[tid + 3 * NT] = make_float4(b1[0], b1[1], b1[2], b1[3]);
}

extern "C" void kernel_launch(void* const* d_in, const int* in_sizes, int n_in,
                              void* d_out, int out_size) {
    const float* x = (const float*)d_in[0];

    prep_kernel<<<1, 256>>>((const float*)d_in[1], (const float*)d_in[2],
                            (const float*)d_in[3], (const float*)d_in[4],
                            (const float*)d_in[5], (const float*)d_in[6],
                            (const float*)d_in[7], (const float*)d_in[8]);

    const int B = in_sizes[0] / KDIM;        // 524288
    const int nblocks = B / EPB;             // 2048

    cudaFuncSetAttribute(olcnn_kernel, cudaFuncAttributeMaxDynamicSharedMemorySize,
                         SMEM_BYTES);
    olcnn_kernel<<<nblocks, NT, SMEM_BYTES>>>(x, (float*)d_out);
}

// round 6
// speedup vs baseline: 1.5706x; 1.5706x over previous
#include <cuda_runtime.h>
#include <cuda_fp16.h>

// OLCNN fused grouped-MLP, round 5.
// R4 post-mortem: 4 elem/thread spilled (255 regs). Revert to proven R3 body
// (2 elem/thread packed f32x2, 92 regs) and keep only the validated R4 idea:
//   - weights in smem instead of __constant__ (kills the LDC rt-8 port bottleneck
//     that exactly explained R3's 63.8us)
//   - weight rows padded to 10 ull -> 16B-aligned -> LDS.128 pair loads
//   - fp16 element-major input staging (stride 82 halfs)
//   - folded-tanh network (validated R2-R4)

typedef unsigned long long ull;

#define NT    128     // threads per block
#define EPB   256     // elements per block (2 per thread)
#define KDIM  81
#define KPAD  82      // element stride in halfs (164 B)

// padded packed-weight blob offsets (ull units; all row starts even -> 16B aligned)
#define OFF_WC 0      // 81 rows x 10
#define OFF_BC 810    // 81 (+1 pad)
#define OFF_WH 892    // 27 rows x 10
#define OFF_BH 1162   // 27 (+1 pad)
#define OFF_WM 1190   // 12 rows x 10
#define OFF_BM 1310   // 12
#define OFF_WO 1322   // 4 rows x 4
#define OFF_BO 1338   // 4
#define NPREP  1344

__device__ ull gPrep[NPREP];

__device__ __forceinline__ ull dupf(float v) {
    unsigned int b = __float_as_uint(v);
    return ((ull)b << 32) | (ull)b;
}

// Fold sigmoid(a)=0.5*tanh(a/2)+0.5 through the network (validated R2-R4).
__global__ void prep_kernel(const float* __restrict__ Wc, const float* __restrict__ bc,
                            const float* __restrict__ Wh, const float* __restrict__ bh,
                            const float* __restrict__ Wm, const float* __restrict__ bm,
                            const float* __restrict__ Wo, const float* __restrict__ bo) {
    int t = threadIdx.x;
    // conv weights: row r = g*9+k, padded stride 10
    for (int i = t; i < 729; i += blockDim.x) {
        int r = i / 9, p = i - r * 9;
        gPrep[OFF_WC + r * 10 + p] = dupf(0.5f * Wc[i]);
    }
    for (int i = t; i < 81;  i += blockDim.x) gPrep[OFF_BC + i] = dupf(0.5f * bc[i]);
    for (int i = t; i < 243; i += blockDim.x) {
        int r = i / 9, p = i - r * 9;
        gPrep[OFF_WH + r * 10 + p] = dupf(0.25f * Wh[i]);
    }
    for (int i = t; i < 27;  i += blockDim.x) {
        float s = 0.f;
        #pragma unroll
        for (int p = 0; p < 9; p++) s += Wh[i * 9 + p];
        gPrep[OFF_BH + i] = dupf(0.5f * bh[i] + 0.25f * s);
    }
    for (int i = t; i < 108; i += blockDim.x) {
        int r = i / 9, p = i - r * 9;
        gPrep[OFF_WM + r * 10 + p] = dupf(0.25f * Wm[i]);
    }
    for (int i = t; i < 12;  i += blockDim.x) {
        float s = 0.f;
        #pragma unroll
        for (int p = 0; p < 9; p++) s += Wm[i * 9 + p];
        gPrep[OFF_BM + i] = dupf(0.5f * bm[i] + 0.25f * s);
    }
    for (int i = t; i < 16;  i += blockDim.x) gPrep[OFF_WO + i] = dupf(0.5f * Wo[i]);
    for (int i = t; i < 4;   i += blockDim.x) {
        float s = 0.f;
        #pragma unroll
        for (int p = 0; p < 4; p++) s += Wo[i * 4 + p];
        gPrep[OFF_BO + i] = dupf(bo[i] + 0.5f * s);
    }
}

__device__ __forceinline__ ull ffma2(ull a, ull b, ull c) {
    ull d;
    asm("fma.rn.f32x2 %0, %1, %2, %3;" : "=l"(d) : "l"(a), "l"(b), "l"(c));
    return d;
}
__device__ __forceinline__ ull pack2(float lo, float hi) {
    ull r;
    asm("mov.b64 %0, {%1, %2};" : "=l"(r) : "f"(lo), "f"(hi));
    return r;
}
__device__ __forceinline__ void unpack2(ull v, float& lo, float& hi) {
    asm("mov.b64 {%0, %1}, %2;" : "=f"(lo), "=f"(hi) : "l"(v));
}
__device__ __forceinline__ ull tanh2(ull v) {
    float lo, hi;
    unpack2(v, lo, hi);
    asm("tanh.approx.f32 %0, %0;" : "+f"(lo));
    asm("tanh.approx.f32 %0, %0;" : "+f"(hi));
    return pack2(lo, hi);
}

// 9-weight dot against a padded 10-ull row using LDS.128 pairs.
__device__ __forceinline__ ull dot9(const ull* __restrict__ row, const ull* __restrict__ v, ull acc) {
    const ulonglong2* r2 = reinterpret_cast<const ulonglong2*>(row);
    ulonglong2 w01 = r2[0], w23 = r2[1], w45 = r2[2], w67 = r2[3];
    ull w8 = row[8];
    acc = ffma2(v[0], w01.x, acc);
    acc = ffma2(v[1], w01.y, acc);
    acc = ffma2(v[2], w23.x, acc);
    acc = ffma2(v[3], w23.y, acc);
    acc = ffma2(v[4], w45.x, acc);
    acc = ffma2(v[5], w45.y, acc);
    acc = ffma2(v[6], w67.x, acc);
    acc = ffma2(v[7], w67.y, acc);
    acc = ffma2(v[8], w8,    acc);
    return acc;
}

// dynamic smem: [ ws: NPREP ull ][ xs: EPB*KPAD half ]
#define SMEM_BYTES (NPREP * 8 + EPB * KPAD * 2)

__global__ __launch_bounds__(NT, 4)
void olcnn_kernel(const float* __restrict__ x, float* __restrict__ out) {
    extern __shared__ ull smem_raw[];
    ull*    ws = smem_raw;
    __half* xs = reinterpret_cast<__half*>(smem_raw + NPREP);

    const int tid = threadIdx.x;
    const long long blk = blockIdx.x;

    // ---- stage weights (L2-hot, 10.75 KB) ----
    #pragma unroll
    for (int i = 0; i < (NPREP + NT - 1) / NT; i++) {
        int idx = i * NT + tid;
        if (idx < NPREP) ws[idx] = gPrep[idx];
    }

    // ---- stage inputs: coalesced float4 -> fp16, element stride KPAD ----
    {
        const float4* __restrict__ src =
            reinterpret_cast<const float4*>(x + blk * (long long)(EPB * KDIM));
        for (int i = tid; i < (EPB * KDIM) / 4; i += NT) {
            float4 v = src[i];
            int f = i * 4;
            int e = f / KDIM;
            int k = f - e * KDIM;
            if (k <= KDIM - 4) {
                __half* d = xs + e * KPAD + k;
                d[0] = __float2half_rn(v.x);
                d[1] = __float2half_rn(v.y);
                d[2] = __float2half_rn(v.z);
                d[3] = __float2half_rn(v.w);
            } else {
                float vv[4] = {v.x, v.y, v.z, v.w};
                #pragma unroll
                for (int j = 0; j < 4; j++) {
                    int kk = k + j, ee = e;
                    if (kk >= KDIM) { kk -= KDIM; ee++; }
                    xs[ee * KPAD + kk] = __float2half_rn(vv[j]);
                }
            }
        }
    }
    __syncthreads();

    // thread handles elements e0=tid, e1=tid+128
    const __half* __restrict__ xa = xs + tid * KPAD;
    const __half* __restrict__ xb = xs + (tid + NT) * KPAD;

    ull lg[4];
    #pragma unroll
    for (int c = 0; c < 4; c++) lg[c] = ws[OFF_BO + c];

    #pragma unroll
    for (int G = 0; G < 3; G++) {
        ull h[9];

        #pragma unroll
        for (int s = 0; s < 3; s++) {
            const int g  = 3 * G + s;
            const int gr = g / 3, gc = g % 3;

            // 9 patch pixels, packed {e0, e1}
            ull px[9];
            #pragma unroll
            for (int p = 0; p < 9; p++) {
                const int k = (3 * gr + p / 3) * 9 + (3 * gc + p % 3);
                px[p] = pack2(__half2float(xa[k]), __half2float(xb[k]));
            }

            // conv: 9 kernels -> tanh
            ull f[9];
            #pragma unroll
            for (int k = 0; k < 9; k++)
                f[k] = tanh2(dot9(ws + OFF_WC + (g * 9 + k) * 10, px,
                                  ws[OFF_BC + g * 9 + k]));

            // hidden: 3 neurons -> tanh
            #pragma unroll
            for (int n = 0; n < 3; n++)
                h[s * 3 + n] = tanh2(dot9(ws + OFF_WH + (g * 3 + n) * 10, f,
                                          ws[OFF_BH + g * 3 + n]));
        }

        // middle group G: 4 neurons -> tanh -> fold into logits
        #pragma unroll
        for (int n = 0; n < 4; n++) {
            ull mv = tanh2(dot9(ws + OFF_WM + (G * 4 + n) * 10, h,
                                ws[OFF_BM + G * 4 + n]));
            lg[G] = ffma2(mv, ws[OFF_WO + G * 4 + n], lg[G]);
            if (G == 0)
                lg[3] = ffma2(mv, ws[OFF_WO + 3 * 4 + n], lg[3]);
        }
    }

    float lo[4], hi[4];
    #pragma unroll
    for (int c = 0; c < 4; c++) unpack2(lg[c], lo[c], hi[c]);

    float4* __restrict__ o4 = reinterpret_cast<float4*>(out) + blk * EPB;
    o4[tid]      = make_float4(lo[0], lo[1], lo[2], lo[3]);
    o4[tid + NT] = make_float4(hi[0], hi[1], hi[2], hi[3]);
}

extern "C" void kernel_launch(void* const* d_in, const int* in_sizes, int n_in,
                              void* d_out, int out_size) {
    const float* x = (const float*)d_in[0];

    prep_kernel<<<1, 256>>>((const float*)d_in[1], (const float*)d_in[2],
                            (const float*)d_in[3], (const float*)d_in[4],
                            (const float*)d_in[5], (const float*)d_in[6],
                            (const float*)d_in[7], (const float*)d_in[8]);

    const int B = in_sizes[0] / KDIM;        // 524288
    const int nblocks = B / EPB;             // 2048

    cudaFuncSetAttribute(olcnn_kernel, cudaFuncAttributeMaxDynamicSharedMemorySize,
                         SMEM_BYTES);
    olcnn_kernel<<<nblocks, NT, SMEM_BYTES>>>(x, (float*)d_out);
}